// round 6
// baseline (speedup 1.0000x reference)
#include <cuda_runtime.h>
#include <cuda_bf16.h>
#include <math.h>

// Problem constants (from reference)
#define NNODES 50000
#define NFEAT  512
#define NHID   128
#define NCLASS 40
#define MAXE   1600000

// Scratch (device globals: the sanctioned no-alloc workspace)
__device__ float g_xw1 [NNODES * NHID];   // x @ W1
__device__ float g_acc1[NNODES * NHID];   // spmm(x@W1)
__device__ float g_hw2 [NNODES * NCLASS]; // relu(acc1+b1) @ W2
__device__ float g_acc2[NNODES * NCLASS]; // spmm(h@W2)

// CSR workspace
__device__ int   g_deg [NNODES];
__device__ int   g_off [NNODES + 1];
__device__ int   g_pos [NNODES];
__device__ int   g_bsum[256];
__device__ int   g_csrc[MAXE];
__device__ float g_cw  [MAXE];

// ---------------------------------------------------------------------------
// Packed fp32x2 FMA (sm_100+)
// ---------------------------------------------------------------------------
__device__ __forceinline__ float2 ffma2(float2 a, float2 b, float2 c) {
    unsigned long long ua = *(unsigned long long*)&a;
    unsigned long long ub = *(unsigned long long*)&b;
    unsigned long long uc = *(unsigned long long*)&c;
    unsigned long long ud;
    asm("fma.rn.f32x2 %0, %1, %2, %3;" : "=l"(ud) : "l"(ua), "l"(ub), "l"(uc));
    return *(float2*)&ud;
}

__device__ __forceinline__ void cp_async16(void* smem_dst, const void* gsrc) {
    unsigned int d = (unsigned int)__cvta_generic_to_shared(smem_dst);
    asm volatile("cp.async.ca.shared.global [%0], [%1], 16;"
                 :: "r"(d), "l"(gsrc));
}

// ===========================================================================
// CSR construction: zero-deg -> histogram -> 3-step scan -> scatter
// ===========================================================================
__global__ void zdeg_kernel(int n) {
    int i = blockIdx.x * blockDim.x + threadIdx.x;
    if (i < n) g_deg[i] = 0;
}

__global__ void hist_kernel(const int* __restrict__ ed, int E) {
    int e = blockIdx.x * blockDim.x + threadIdx.x;
    if (e < E) atomicAdd(&g_deg[ed[e]], 1);
}

__global__ void scan1_kernel(int n) {          // per-block inclusive scan
    __shared__ int sh[256];
    int t = threadIdx.x, i = blockIdx.x * 256 + t;
    int v = (i < n) ? g_deg[i] : 0;
    sh[t] = v; __syncthreads();
    for (int o = 1; o < 256; o <<= 1) {
        int u = (t >= o) ? sh[t - o] : 0;
        __syncthreads();
        sh[t] += u;
        __syncthreads();
    }
    if (i < n) g_off[i + 1] = sh[t];
    if (t == 255) g_bsum[blockIdx.x] = sh[255];
}

__global__ void scan2_kernel(int nb) {         // exclusive scan of block sums
    __shared__ int sh[256];
    int t = threadIdx.x;
    sh[t] = (t < nb) ? g_bsum[t] : 0; __syncthreads();
    for (int o = 1; o < 256; o <<= 1) {
        int u = (t >= o) ? sh[t - o] : 0;
        __syncthreads();
        sh[t] += u;
        __syncthreads();
    }
    int excl = (t == 0) ? 0 : sh[t - 1];
    if (t < nb) g_bsum[t] = excl;
}

__global__ void scan3_kernel(int n) {          // add block prefix; zero cursors
    int i = blockIdx.x * 256 + threadIdx.x;
    if (i < n) {
        g_off[i + 1] += g_bsum[blockIdx.x];
        g_pos[i] = 0;
    }
    if (i == 0) g_off[0] = 0;
}

__global__ void scatter_kernel(const int* __restrict__ es,
                               const int* __restrict__ ed,
                               const float* __restrict__ ev, int E) {
    int e = blockIdx.x * blockDim.x + threadIdx.x;
    if (e >= E) return;
    int d = ed[e];
    int idx = g_off[d] + atomicAdd(&g_pos[d], 1);
    g_csrc[idx] = es[e];
    g_cw[idx]   = ev[e];
}

// ---------------------------------------------------------------------------
// GEMM1: C[M,128] = A[M,512] @ B[512,128]
// fp32, 128x128x16 tiles, double-buffered (cp.async for B), f32x2 FMAs.
// ---------------------------------------------------------------------------
#define BM 128
#define BN 128
#define BK 16
#define TM 8
#define TN 8

__global__ __launch_bounds__(256, 2) void sgemm1_kernel(
    const float* __restrict__ A, const float* __restrict__ B,
    float* __restrict__ C, int M)
{
    __shared__ float As[2][BK][BM];   // [k][row]
    __shared__ float Bs[2][BK][BN];   // [k][col]

    const int K = NFEAT;   // 512
    const int N = NHID;    // 128
    const int NT = K / BK; // 32

    int tid = threadIdx.x;
    int block_row = blockIdx.x * BM;

    int tx = tid & 15;
    int ty = tid >> 4;

    // A tile: 128 rows x 16 k = 512 float4; 2 per thread.
    // float4 idx i: row = i>>2, kq = (i&3)*4
    int ar0 = tid >> 2,          ak0 = (tid & 3) * 4;
    int ar1 = (tid + 256) >> 2,  ak1 = (tid & 3) * 4;  // (i+256)&3 == i&3
    // B tile: 16 k x 128 cols = 512 float4; 2 per thread.
    // idx i: k = i>>5, col = (i&31)*4
    int bk0 = tid >> 5,          bc0 = (tid & 31) * 4;
    int bk1 = (tid + 256) >> 5,  bc1 = (tid & 31) * 4;

    int grow0 = block_row + ar0;
    int grow1 = block_row + ar1;

    float2 accp[TM][TN / 2];
#pragma unroll
    for (int i = 0; i < TM; i++)
#pragma unroll
        for (int j = 0; j < TN / 2; j++) accp[i][j] = make_float2(0.f, 0.f);

#define LOAD_TILE(k0, buf)                                                    \
    do {                                                                      \
        float4 v0 = (grow0 < M)                                               \
            ? *(const float4*)(A + (size_t)grow0 * K + (k0) + ak0)            \
            : make_float4(0.f, 0.f, 0.f, 0.f);                                \
        float4 v1 = (grow1 < M)                                               \
            ? *(const float4*)(A + (size_t)grow1 * K + (k0) + ak1)            \
            : make_float4(0.f, 0.f, 0.f, 0.f);                                \
        As[buf][ak0 + 0][ar0] = v0.x;                                         \
        As[buf][ak0 + 1][ar0] = v0.y;                                         \
        As[buf][ak0 + 2][ar0] = v0.z;                                         \
        As[buf][ak0 + 3][ar0] = v0.w;                                         \
        As[buf][ak1 + 0][ar1] = v1.x;                                         \
        As[buf][ak1 + 1][ar1] = v1.y;                                         \
        As[buf][ak1 + 2][ar1] = v1.z;                                         \
        As[buf][ak1 + 3][ar1] = v1.w;                                         \
        cp_async16(&Bs[buf][bk0][bc0], B + (size_t)((k0) + bk0) * N + bc0);   \
        cp_async16(&Bs[buf][bk1][bc1], B + (size_t)((k0) + bk1) * N + bc1);   \
        asm volatile("cp.async.commit_group;");                               \
    } while (0)

    LOAD_TILE(0, 0);

    for (int t = 0; t < NT; t++) {
        asm volatile("cp.async.wait_group 0;");
        __syncthreads();
        int cur = t & 1;
        if (t + 1 < NT) {
            int nb = (t + 1) & 1;
            LOAD_TILE((t + 1) * BK, nb);
        }
#pragma unroll
        for (int k = 0; k < BK; k++) {
            float ar[TM];
            float2 br2[TN / 2];
#pragma unroll
            for (int i = 0; i < TM; i += 4)
                *(float4*)&ar[i] = *(const float4*)&As[cur][k][ty * TM + i];
#pragma unroll
            for (int j = 0; j < TN / 2; j += 2)
                *(float4*)&br2[j] = *(const float4*)&Bs[cur][k][tx * TN + j * 2];
#pragma unroll
            for (int i = 0; i < TM; i++) {
                float2 a2 = make_float2(ar[i], ar[i]);
#pragma unroll
                for (int j = 0; j < TN / 2; j++)
                    accp[i][j] = ffma2(a2, br2[j], accp[i][j]);
            }
        }
        __syncthreads();
    }
#undef LOAD_TILE

#pragma unroll
    for (int i = 0; i < TM; i++) {
        int row = block_row + ty * TM + i;
        if (row < M) {
            *(float4*)(C + (size_t)row * N + tx * TN)     = *(float4*)&accp[i][0];
            *(float4*)(C + (size_t)row * N + tx * TN + 4) = *(float4*)&accp[i][2];
        }
    }
}

// ---------------------------------------------------------------------------
// SpMM (128 feats) over CSR: one warp per dst row, register accumulation.
// ---------------------------------------------------------------------------
__global__ void spmm128_csr_kernel(const float* __restrict__ feat,
                                   float* __restrict__ out, int M)
{
    int warp = (blockIdx.x * blockDim.x + threadIdx.x) >> 5;
    int lane = threadIdx.x & 31;
    if (warp >= M) return;
    int beg = g_off[warp], end = g_off[warp + 1];

    const float* base = feat + lane * 4;
    float2 a0 = make_float2(0.f, 0.f), a1 = make_float2(0.f, 0.f);

    int j = beg;
    for (; j + 4 <= end; j += 4) {
        int   s0 = g_csrc[j],     s1 = g_csrc[j + 1];
        int   s2 = g_csrc[j + 2], s3 = g_csrc[j + 3];
        float w0 = g_cw[j],     w1 = g_cw[j + 1];
        float w2 = g_cw[j + 2], w3 = g_cw[j + 3];
        float4 v0 = *(const float4*)(base + (size_t)s0 * NHID);
        float4 v1 = *(const float4*)(base + (size_t)s1 * NHID);
        float4 v2 = *(const float4*)(base + (size_t)s2 * NHID);
        float4 v3 = *(const float4*)(base + (size_t)s3 * NHID);
        a0 = ffma2(make_float2(w0, w0), make_float2(v0.x, v0.y), a0);
        a1 = ffma2(make_float2(w0, w0), make_float2(v0.z, v0.w), a1);
        a0 = ffma2(make_float2(w1, w1), make_float2(v1.x, v1.y), a0);
        a1 = ffma2(make_float2(w1, w1), make_float2(v1.z, v1.w), a1);
        a0 = ffma2(make_float2(w2, w2), make_float2(v2.x, v2.y), a0);
        a1 = ffma2(make_float2(w2, w2), make_float2(v2.z, v2.w), a1);
        a0 = ffma2(make_float2(w3, w3), make_float2(v3.x, v3.y), a0);
        a1 = ffma2(make_float2(w3, w3), make_float2(v3.z, v3.w), a1);
    }
    for (; j < end; j++) {
        int   s = g_csrc[j];
        float w = g_cw[j];
        float4 v = *(const float4*)(base + (size_t)s * NHID);
        a0 = ffma2(make_float2(w, w), make_float2(v.x, v.y), a0);
        a1 = ffma2(make_float2(w, w), make_float2(v.z, v.w), a1);
    }

    float4 r = make_float4(a0.x, a0.y, a1.x, a1.y);
    *(float4*)(out + (size_t)warp * NHID + lane * 4) = r;
}

// ---------------------------------------------------------------------------
// SpMM (40 feats) over CSR: one half-warp per dst row; lanes 0..9 active.
// ---------------------------------------------------------------------------
__global__ void spmm40_csr_kernel(const float* __restrict__ feat,
                                  float* __restrict__ out, int M)
{
    int g    = (blockIdx.x * blockDim.x + threadIdx.x) >> 4;
    int l16  = threadIdx.x & 15;
    if (g >= M) return;
    int beg = g_off[g], end = g_off[g + 1];
    bool act = l16 < 10;

    const float* base = feat + l16 * 4;
    float2 a0 = make_float2(0.f, 0.f), a1 = make_float2(0.f, 0.f);
    float4 z = make_float4(0.f, 0.f, 0.f, 0.f);

    int j = beg;
    for (; j + 4 <= end; j += 4) {
        int   s0 = g_csrc[j],     s1 = g_csrc[j + 1];
        int   s2 = g_csrc[j + 2], s3 = g_csrc[j + 3];
        float w0 = g_cw[j],     w1 = g_cw[j + 1];
        float w2 = g_cw[j + 2], w3 = g_cw[j + 3];
        float4 v0 = act ? *(const float4*)(base + (size_t)s0 * NCLASS) : z;
        float4 v1 = act ? *(const float4*)(base + (size_t)s1 * NCLASS) : z;
        float4 v2 = act ? *(const float4*)(base + (size_t)s2 * NCLASS) : z;
        float4 v3 = act ? *(const float4*)(base + (size_t)s3 * NCLASS) : z;
        a0 = ffma2(make_float2(w0, w0), make_float2(v0.x, v0.y), a0);
        a1 = ffma2(make_float2(w0, w0), make_float2(v0.z, v0.w), a1);
        a0 = ffma2(make_float2(w1, w1), make_float2(v1.x, v1.y), a0);
        a1 = ffma2(make_float2(w1, w1), make_float2(v1.z, v1.w), a1);
        a0 = ffma2(make_float2(w2, w2), make_float2(v2.x, v2.y), a0);
        a1 = ffma2(make_float2(w2, w2), make_float2(v2.z, v2.w), a1);
        a0 = ffma2(make_float2(w3, w3), make_float2(v3.x, v3.y), a0);
        a1 = ffma2(make_float2(w3, w3), make_float2(v3.z, v3.w), a1);
    }
    for (; j < end; j++) {
        int   s = g_csrc[j];
        float w = g_cw[j];
        float4 v = act ? *(const float4*)(base + (size_t)s * NCLASS) : z;
        a0 = ffma2(make_float2(w, w), make_float2(v.x, v.y), a0);
        a1 = ffma2(make_float2(w, w), make_float2(v.z, v.w), a1);
    }

    if (act) {
        float4 r = make_float4(a0.x, a0.y, a1.x, a1.y);
        *(float4*)(out + (size_t)g * NCLASS + l16 * 4) = r;
    }
}

// ---------------------------------------------------------------------------
// GEMM2: hw2[r,:] = relu(acc1[r,:] + b1) @ W2   (M x 128 @ 128 x 40)
// 128-row blocks; each thread computes 2 rows x 10 cols (double ILP).
// W2 staged in smem; acc1 tile staged with fused bias+ReLU.
// ---------------------------------------------------------------------------
#define G2_ROWS 128
#define G2_APAD 132
#define G2_SMEM_FLOATS (NHID * NCLASS + G2_ROWS * G2_APAD)

__global__ __launch_bounds__(256) void gemm2_kernel(
    const float* __restrict__ acc1, const float* __restrict__ b1,
    const float* __restrict__ W2, float* __restrict__ hw2, int M)
{
    extern __shared__ float sm[];
    float* Ws = sm;                     // [128][40]
    float* At = sm + NHID * NCLASS;     // [128][132]

    int tid = threadIdx.x;
    int row0 = blockIdx.x * G2_ROWS;

#pragma unroll
    for (int i = 0; i < NHID * NCLASS / 256; i++)
        Ws[tid + i * 256] = W2[tid + i * 256];

#pragma unroll
    for (int i = 0; i < G2_ROWS * NHID / (256 * 4); i++) {
        int idx4 = tid + i * 256;
        int r    = idx4 >> 5;
        int c4   = idx4 & 31;
        int grow = row0 + r;
        float4 v = (grow < M)
            ? *(const float4*)(acc1 + (size_t)grow * NHID + c4 * 4)
            : make_float4(0.f, 0.f, 0.f, 0.f);
        float4 b = *(const float4*)(b1 + c4 * 4);
        float4 h;
        h.x = fmaxf(v.x + b.x, 0.f);
        h.y = fmaxf(v.y + b.y, 0.f);
        h.z = fmaxf(v.z + b.z, 0.f);
        h.w = fmaxf(v.w + b.w, 0.f);
        *(float4*)(At + r * G2_APAD + c4 * 4) = h;
    }
    __syncthreads();

    int r  = tid >> 2;          // 0..63 -> rows r and r+64
    int qc = (tid & 3) * 10;

    float2 accA[5], accB[5];
#pragma unroll
    for (int j = 0; j < 5; j++) {
        accA[j] = make_float2(0.f, 0.f);
        accB[j] = make_float2(0.f, 0.f);
    }

    const float* arowA = At + r * G2_APAD;
    const float* arowB = At + (r + 64) * G2_APAD;
#pragma unroll 4
    for (int k = 0; k < NHID; k += 4) {
        float4 ha = *(const float4*)(arowA + k);
        float4 hb = *(const float4*)(arowB + k);
#pragma unroll
        for (int kk = 0; kk < 4; kk++) {
            float2 h2a = make_float2((&ha.x)[kk], (&ha.x)[kk]);
            float2 h2b = make_float2((&hb.x)[kk], (&hb.x)[kk]);
            const float* wrow = Ws + (k + kk) * NCLASS + qc;
#pragma unroll
            for (int j = 0; j < 5; j++) {
                float2 w = *(const float2*)(wrow + j * 2);
                accA[j] = ffma2(h2a, w, accA[j]);
                accB[j] = ffma2(h2b, w, accB[j]);
            }
        }
    }

    int growA = row0 + r;
    int growB = row0 + r + 64;
    if (growA < M) {
        float* o = hw2 + (size_t)growA * NCLASS + qc;
#pragma unroll
        for (int j = 0; j < 5; j++) *(float2*)(o + j * 2) = accA[j];
    }
    if (growB < M) {
        float* o = hw2 + (size_t)growB * NCLASS + qc;
#pragma unroll
        for (int j = 0; j < 5; j++) *(float2*)(o + j * 2) = accB[j];
    }
}

// ---------------------------------------------------------------------------
// Final: out = log_softmax(acc2 + b2). One warp per row of 40.
// ---------------------------------------------------------------------------
__global__ __launch_bounds__(256) void lsm_kernel(
    const float* __restrict__ acc2, const float* __restrict__ b2,
    float* __restrict__ out, int M)
{
    int warp = (blockIdx.x * blockDim.x + threadIdx.x) >> 5;
    int lane = threadIdx.x & 31;
    if (warp >= M) return;
    const float* r = acc2 + (size_t)warp * NCLASS;
    float v0 = r[lane] + __ldg(b2 + lane);
    float v1 = (lane < 8) ? (r[lane + 32] + __ldg(b2 + lane + 32)) : -INFINITY;
    float m = fmaxf(v0, v1);
#pragma unroll
    for (int o = 16; o > 0; o >>= 1)
        m = fmaxf(m, __shfl_xor_sync(0xFFFFFFFFu, m, o));
    float s = expf(v0 - m) + ((lane < 8) ? expf(v1 - m) : 0.f);
#pragma unroll
    for (int o = 16; o > 0; o >>= 1)
        s += __shfl_xor_sync(0xFFFFFFFFu, s, o);
    float lse = m + logf(s);
    out[(size_t)warp * NCLASS + lane] = v0 - lse;
    if (lane < 8) out[(size_t)warp * NCLASS + lane + 32] = v1 - lse;
}

// ---------------------------------------------------------------------------

extern "C" void kernel_launch(void* const* d_in, const int* in_sizes, int n_in,
                              void* d_out, int out_size)
{
    const float* x  = (const float*)d_in[0];
    const float* W1 = (const float*)d_in[1];
    const float* b1 = (const float*)d_in[2];
    const float* W2 = (const float*)d_in[3];
    const float* b2 = (const float*)d_in[4];
    const int*   es = (const int*)d_in[5];
    const int*   ed = (const int*)d_in[6];
    const float* ev = (const float*)d_in[7];
    int E = in_sizes[5];
    float* out = (float*)d_out;
    int M = NNODES;

    float *p_xw1, *p_acc1, *p_hw2, *p_acc2;
    cudaGetSymbolAddress((void**)&p_xw1,  g_xw1);
    cudaGetSymbolAddress((void**)&p_acc1, g_acc1);
    cudaGetSymbolAddress((void**)&p_hw2,  g_hw2);
    cudaGetSymbolAddress((void**)&p_acc2, g_acc2);

    const int g2_smem = G2_SMEM_FLOATS * sizeof(float);   // ~86 KB
    cudaFuncSetAttribute(gemm2_kernel,
                         cudaFuncAttributeMaxDynamicSharedMemorySize, g2_smem);

    int nb = (M + 255) / 256;   // 196 blocks (<=256 required by scan2)

    // --- CSR build (used by both SpMM layers) ---
    zdeg_kernel<<<nb, 256>>>(M);
    hist_kernel<<<(E + 255) / 256, 256>>>(ed, E);
    scan1_kernel<<<nb, 256>>>(M);
    scan2_kernel<<<1, 256>>>(nb);
    scan3_kernel<<<nb, 256>>>(M);
    scatter_kernel<<<(E + 255) / 256, 256>>>(es, ed, ev, E);

    // --- layer 1 ---
    sgemm1_kernel<<<(M + BM - 1) / BM, 256>>>(x, W1, p_xw1, M);
    spmm128_csr_kernel<<<(M * 32 + 255) / 256, 256>>>(p_xw1, p_acc1, M);

    // --- layer 2 ---
    gemm2_kernel<<<(M + G2_ROWS - 1) / G2_ROWS, 256, g2_smem>>>(
        p_acc1, b1, W2, p_hw2, M);
    spmm40_csr_kernel<<<(M * 16 + 255) / 256, 256>>>(p_hw2, p_acc2, M);

    // --- epilogue ---
    lsm_kernel<<<(M * 32 + 255) / 256, 256>>>(p_acc2, b2, out, M);
}

// round 7
// speedup vs baseline: 1.4235x; 1.4235x over previous
#include <cuda_runtime.h>
#include <cuda_bf16.h>
#include <math.h>

// Problem constants (from reference)
#define NNODES 50000
#define NFEAT  512
#define NHID   128
#define NCLASS 40
#define MAXE   1600000

// Scratch (device globals: the sanctioned no-alloc workspace)
__device__ float g_xw1 [NNODES * NHID];   // x @ W1
__device__ float g_acc1[NNODES * NHID];   // spmm(x@W1)
__device__ float g_hw2 [NNODES * NCLASS]; // relu(acc1+b1) @ W2

// CSR workspace
__device__ int   g_deg [NNODES];
__device__ int   g_off [NNODES + 1];
__device__ int   g_pos [NNODES];
__device__ int   g_bsum[256];
__device__ int   g_csrc[MAXE];
__device__ float g_cw  [MAXE];

// ---------------------------------------------------------------------------
// Packed fp32x2 FMA (sm_100+)
// ---------------------------------------------------------------------------
__device__ __forceinline__ float2 ffma2(float2 a, float2 b, float2 c) {
    unsigned long long ua = *(unsigned long long*)&a;
    unsigned long long ub = *(unsigned long long*)&b;
    unsigned long long uc = *(unsigned long long*)&c;
    unsigned long long ud;
    asm("fma.rn.f32x2 %0, %1, %2, %3;" : "=l"(ud) : "l"(ua), "l"(ub), "l"(uc));
    return *(float2*)&ud;
}

// ===========================================================================
// CSR construction: zero-deg -> histogram -> 3-step scan -> scatter
// ===========================================================================
__global__ void zdeg_kernel(int n) {
    int i = blockIdx.x * blockDim.x + threadIdx.x;
    if (i < n) g_deg[i] = 0;
}

__global__ void hist_kernel(const int* __restrict__ ed, int E) {
    int e = blockIdx.x * blockDim.x + threadIdx.x;
    if (e < E) atomicAdd(&g_deg[ed[e]], 1);
}

__global__ void scan1_kernel(int n) {          // per-block inclusive scan
    __shared__ int sh[256];
    int t = threadIdx.x, i = blockIdx.x * 256 + t;
    int v = (i < n) ? g_deg[i] : 0;
    sh[t] = v; __syncthreads();
    for (int o = 1; o < 256; o <<= 1) {
        int u = (t >= o) ? sh[t - o] : 0;
        __syncthreads();
        sh[t] += u;
        __syncthreads();
    }
    if (i < n) g_off[i + 1] = sh[t];
    if (t == 255) g_bsum[blockIdx.x] = sh[255];
}

__global__ void scan2_kernel(int nb) {         // exclusive scan of block sums
    __shared__ int sh[256];
    int t = threadIdx.x;
    sh[t] = (t < nb) ? g_bsum[t] : 0; __syncthreads();
    for (int o = 1; o < 256; o <<= 1) {
        int u = (t >= o) ? sh[t - o] : 0;
        __syncthreads();
        sh[t] += u;
        __syncthreads();
    }
    int excl = (t == 0) ? 0 : sh[t - 1];
    if (t < nb) g_bsum[t] = excl;
}

__global__ void scan3_kernel(int n) {          // add block prefix; zero cursors
    int i = blockIdx.x * 256 + threadIdx.x;
    if (i < n) {
        g_off[i + 1] += g_bsum[blockIdx.x];
        g_pos[i] = 0;
    }
    if (i == 0) g_off[0] = 0;
}

__global__ void scatter_kernel(const int* __restrict__ es,
                               const int* __restrict__ ed,
                               const float* __restrict__ ev, int E) {
    int e = blockIdx.x * blockDim.x + threadIdx.x;
    if (e >= E) return;
    int d = ed[e];
    int idx = g_off[d] + atomicAdd(&g_pos[d], 1);
    g_csrc[idx] = es[e];
    g_cw[idx]   = ev[e];
}

// ---------------------------------------------------------------------------
// GEMM1: C[M,128] = A[M,512] @ B[512,128]
// fp32, 128x128x8 tiles, 8x8 per thread, packed f32x2 accumulation.
// (R5 version — known good.)
// ---------------------------------------------------------------------------
#define BM 128
#define BN 128
#define BK 8
#define TM 8
#define TN 8

__global__ __launch_bounds__(256, 2) void sgemm1_kernel(
    const float* __restrict__ A, const float* __restrict__ B,
    float* __restrict__ C, int M)
{
    __shared__ float As[BK][BM];
    __shared__ float Bs[BK][BN];

    const int K = NFEAT;
    const int N = NHID;

    int tid = threadIdx.x;
    int block_row = blockIdx.x * BM;

    int tx = tid & 15;
    int ty = tid >> 4;

    int a_row = tid >> 1;
    int a_k   = (tid & 1) * 4;
    int b_k   = tid >> 5;
    int b_col = (tid & 31) * 4;

    int grow = block_row + a_row;

    float2 accp[TM][TN / 2];
#pragma unroll
    for (int i = 0; i < TM; i++)
#pragma unroll
        for (int j = 0; j < TN / 2; j++) accp[i][j] = make_float2(0.f, 0.f);

    for (int k0 = 0; k0 < K; k0 += BK) {
        float4 av = (grow < M)
            ? *(const float4*)(A + (size_t)grow * K + k0 + a_k)
            : make_float4(0.f, 0.f, 0.f, 0.f);
        As[a_k + 0][a_row] = av.x;
        As[a_k + 1][a_row] = av.y;
        As[a_k + 2][a_row] = av.z;
        As[a_k + 3][a_row] = av.w;

        *(float4*)&Bs[b_k][b_col] =
            *(const float4*)(B + (size_t)(k0 + b_k) * N + b_col);

        __syncthreads();

#pragma unroll
        for (int k = 0; k < BK; k++) {
            float ar[TM];
            float2 br2[TN / 2];
#pragma unroll
            for (int i = 0; i < TM; i += 4)
                *(float4*)&ar[i] = *(const float4*)&As[k][ty * TM + i];
#pragma unroll
            for (int j = 0; j < TN / 2; j += 2)
                *(float4*)&br2[j] = *(const float4*)&Bs[k][tx * TN + j * 2];
#pragma unroll
            for (int i = 0; i < TM; i++) {
                float2 a2 = make_float2(ar[i], ar[i]);
#pragma unroll
                for (int j = 0; j < TN / 2; j++)
                    accp[i][j] = ffma2(a2, br2[j], accp[i][j]);
            }
        }
        __syncthreads();
    }

#pragma unroll
    for (int i = 0; i < TM; i++) {
        int row = block_row + ty * TM + i;
        if (row < M) {
            *(float4*)(C + (size_t)row * N + tx * TN)     = *(float4*)&accp[i][0];
            *(float4*)(C + (size_t)row * N + tx * TN + 4) = *(float4*)&accp[i][2];
        }
    }
}

// ---------------------------------------------------------------------------
// SpMM (128 feats) over CSR: one warp per dst row, register accumulation.
// ---------------------------------------------------------------------------
__global__ void spmm128_csr_kernel(const float* __restrict__ feat,
                                   float* __restrict__ out, int M)
{
    int warp = (blockIdx.x * blockDim.x + threadIdx.x) >> 5;
    int lane = threadIdx.x & 31;
    if (warp >= M) return;
    int beg = g_off[warp], end = g_off[warp + 1];

    const float* base = feat + lane * 4;
    float2 a0 = make_float2(0.f, 0.f), a1 = make_float2(0.f, 0.f);

    int j = beg;
    for (; j + 4 <= end; j += 4) {
        int   s0 = g_csrc[j],     s1 = g_csrc[j + 1];
        int   s2 = g_csrc[j + 2], s3 = g_csrc[j + 3];
        float w0 = g_cw[j],     w1 = g_cw[j + 1];
        float w2 = g_cw[j + 2], w3 = g_cw[j + 3];
        float4 v0 = *(const float4*)(base + (size_t)s0 * NHID);
        float4 v1 = *(const float4*)(base + (size_t)s1 * NHID);
        float4 v2 = *(const float4*)(base + (size_t)s2 * NHID);
        float4 v3 = *(const float4*)(base + (size_t)s3 * NHID);
        a0 = ffma2(make_float2(w0, w0), make_float2(v0.x, v0.y), a0);
        a1 = ffma2(make_float2(w0, w0), make_float2(v0.z, v0.w), a1);
        a0 = ffma2(make_float2(w1, w1), make_float2(v1.x, v1.y), a0);
        a1 = ffma2(make_float2(w1, w1), make_float2(v1.z, v1.w), a1);
        a0 = ffma2(make_float2(w2, w2), make_float2(v2.x, v2.y), a0);
        a1 = ffma2(make_float2(w2, w2), make_float2(v2.z, v2.w), a1);
        a0 = ffma2(make_float2(w3, w3), make_float2(v3.x, v3.y), a0);
        a1 = ffma2(make_float2(w3, w3), make_float2(v3.z, v3.w), a1);
    }
    for (; j < end; j++) {
        int   s = g_csrc[j];
        float w = g_cw[j];
        float4 v = *(const float4*)(base + (size_t)s * NHID);
        a0 = ffma2(make_float2(w, w), make_float2(v.x, v.y), a0);
        a1 = ffma2(make_float2(w, w), make_float2(v.z, v.w), a1);
    }

    float4 r = make_float4(a0.x, a0.y, a1.x, a1.y);
    *(float4*)(out + (size_t)warp * NHID + lane * 4) = r;
}

// ---------------------------------------------------------------------------
// SpMM (40 feats) over CSR, FUSED with +b2 and log_softmax.
// One half-warp (16 lanes) per dst row; lanes 0..9 own the 10 float4 chunks.
// After accumulation the half-warp holds the full 40-class row in registers:
// add b2, reduce max / sum-of-exp via width-16 shfl, write final log-probs.
// Geometry is exact: 50000 rows * 16 lanes = 3125 full blocks, no ragged warps.
// ---------------------------------------------------------------------------
__global__ void spmm40_lsm_kernel(const float* __restrict__ feat,
                                  const float* __restrict__ b2,
                                  float* __restrict__ out, int M)
{
    int g    = (blockIdx.x * blockDim.x + threadIdx.x) >> 4;
    int l16  = threadIdx.x & 15;
    if (g >= M) return;
    int beg = g_off[g], end = g_off[g + 1];
    bool act = l16 < 10;

    const float* base = feat + l16 * 4;
    float2 a0 = make_float2(0.f, 0.f), a1 = make_float2(0.f, 0.f);
    float4 z = make_float4(0.f, 0.f, 0.f, 0.f);

    int j = beg;
    for (; j + 4 <= end; j += 4) {
        int   s0 = g_csrc[j],     s1 = g_csrc[j + 1];
        int   s2 = g_csrc[j + 2], s3 = g_csrc[j + 3];
        float w0 = g_cw[j],     w1 = g_cw[j + 1];
        float w2 = g_cw[j + 2], w3 = g_cw[j + 3];
        float4 v0 = act ? *(const float4*)(base + (size_t)s0 * NCLASS) : z;
        float4 v1 = act ? *(const float4*)(base + (size_t)s1 * NCLASS) : z;
        float4 v2 = act ? *(const float4*)(base + (size_t)s2 * NCLASS) : z;
        float4 v3 = act ? *(const float4*)(base + (size_t)s3 * NCLASS) : z;
        a0 = ffma2(make_float2(w0, w0), make_float2(v0.x, v0.y), a0);
        a1 = ffma2(make_float2(w0, w0), make_float2(v0.z, v0.w), a1);
        a0 = ffma2(make_float2(w1, w1), make_float2(v1.x, v1.y), a0);
        a1 = ffma2(make_float2(w1, w1), make_float2(v1.z, v1.w), a1);
        a0 = ffma2(make_float2(w2, w2), make_float2(v2.x, v2.y), a0);
        a1 = ffma2(make_float2(w2, w2), make_float2(v2.z, v2.w), a1);
        a0 = ffma2(make_float2(w3, w3), make_float2(v3.x, v3.y), a0);
        a1 = ffma2(make_float2(w3, w3), make_float2(v3.z, v3.w), a1);
    }
    for (; j < end; j++) {
        int   s = g_csrc[j];
        float w = g_cw[j];
        float4 v = act ? *(const float4*)(base + (size_t)s * NCLASS) : z;
        a0 = ffma2(make_float2(w, w), make_float2(v.x, v.y), a0);
        a1 = ffma2(make_float2(w, w), make_float2(v.z, v.w), a1);
    }

    // logits = acc + b2 (4 per active lane)
    float4 lv;
    if (act) {
        float4 b = *(const float4*)(b2 + l16 * 4);
        lv = make_float4(a0.x + b.x, a0.y + b.y, a1.x + b.z, a1.y + b.w);
    } else {
        lv = make_float4(-INFINITY, -INFINITY, -INFINITY, -INFINITY);
    }

    // width-16 max reduction
    float m = fmaxf(fmaxf(lv.x, lv.y), fmaxf(lv.z, lv.w));
#pragma unroll
    for (int o = 8; o > 0; o >>= 1)
        m = fmaxf(m, __shfl_xor_sync(0xFFFFFFFFu, m, o, 16));

    // width-16 sum-of-exp reduction
    float s = act ? (expf(lv.x - m) + expf(lv.y - m) +
                     expf(lv.z - m) + expf(lv.w - m)) : 0.f;
#pragma unroll
    for (int o = 8; o > 0; o >>= 1)
        s += __shfl_xor_sync(0xFFFFFFFFu, s, o, 16);

    float lse = m + logf(s);

    if (act) {
        float4 r = make_float4(lv.x - lse, lv.y - lse, lv.z - lse, lv.w - lse);
        *(float4*)(out + (size_t)g * NCLASS + l16 * 4) = r;
    }
}

// ---------------------------------------------------------------------------
// GEMM2: hw2[r,:] = relu(acc1[r,:] + b1) @ W2   (M x 128 @ 128 x 40)
// (R5 version — known good: 64-row blocks, W2 + fused-ReLU tile in smem.)
// ---------------------------------------------------------------------------
#define G2_ROWS 64
#define G2_APAD 132
#define G2_SMEM_FLOATS (NHID * NCLASS + G2_ROWS * G2_APAD)

__global__ __launch_bounds__(256) void gemm2_kernel(
    const float* __restrict__ acc1, const float* __restrict__ b1,
    const float* __restrict__ W2, float* __restrict__ hw2, int M)
{
    extern __shared__ float sm[];
    float* Ws = sm;                     // [128][40]
    float* At = sm + NHID * NCLASS;     // [64][132]

    int tid = threadIdx.x;
    int row0 = blockIdx.x * G2_ROWS;

#pragma unroll
    for (int i = 0; i < NHID * NCLASS / 256; i++)
        Ws[tid + i * 256] = W2[tid + i * 256];

#pragma unroll
    for (int i = 0; i < G2_ROWS * NHID / (256 * 4); i++) {
        int idx4 = tid + i * 256;
        int r    = idx4 >> 5;
        int c4   = idx4 & 31;
        int grow = row0 + r;
        float4 v = (grow < M)
            ? *(const float4*)(acc1 + (size_t)grow * NHID + c4 * 4)
            : make_float4(0.f, 0.f, 0.f, 0.f);
        float4 b = *(const float4*)(b1 + c4 * 4);
        float4 h;
        h.x = fmaxf(v.x + b.x, 0.f);
        h.y = fmaxf(v.y + b.y, 0.f);
        h.z = fmaxf(v.z + b.z, 0.f);
        h.w = fmaxf(v.w + b.w, 0.f);
        *(float4*)(At + r * G2_APAD + c4 * 4) = h;
    }
    __syncthreads();

    int r  = tid >> 2;
    int qc = (tid & 3) * 10;

    float2 acc[5];
#pragma unroll
    for (int j = 0; j < 5; j++) acc[j] = make_float2(0.f, 0.f);

    const float* arow = At + r * G2_APAD;
#pragma unroll 4
    for (int k = 0; k < NHID; k += 4) {
        float4 h4 = *(const float4*)(arow + k);
#pragma unroll
        for (int kk = 0; kk < 4; kk++) {
            float h = (&h4.x)[kk];
            float2 h2 = make_float2(h, h);
            const float* wrow = Ws + (k + kk) * NCLASS + qc;
#pragma unroll
            for (int j = 0; j < 5; j++)
                acc[j] = ffma2(h2, *(const float2*)(wrow + j * 2), acc[j]);
        }
    }

    int grow = row0 + r;
    if (grow < M) {
        float* o = hw2 + (size_t)grow * NCLASS + qc;
#pragma unroll
        for (int j = 0; j < 5; j++)
            *(float2*)(o + j * 2) = acc[j];
    }
}

// ---------------------------------------------------------------------------

extern "C" void kernel_launch(void* const* d_in, const int* in_sizes, int n_in,
                              void* d_out, int out_size)
{
    const float* x  = (const float*)d_in[0];
    const float* W1 = (const float*)d_in[1];
    const float* b1 = (const float*)d_in[2];
    const float* W2 = (const float*)d_in[3];
    const float* b2 = (const float*)d_in[4];
    const int*   es = (const int*)d_in[5];
    const int*   ed = (const int*)d_in[6];
    const float* ev = (const float*)d_in[7];
    int E = in_sizes[5];
    float* out = (float*)d_out;
    int M = NNODES;

    float *p_xw1, *p_acc1, *p_hw2;
    cudaGetSymbolAddress((void**)&p_xw1,  g_xw1);
    cudaGetSymbolAddress((void**)&p_acc1, g_acc1);
    cudaGetSymbolAddress((void**)&p_hw2,  g_hw2);

    const int g2_smem = G2_SMEM_FLOATS * sizeof(float);
    cudaFuncSetAttribute(gemm2_kernel,
                         cudaFuncAttributeMaxDynamicSharedMemorySize, g2_smem);

    int nb = (M + 255) / 256;   // 196 blocks (<=256 required by scan2)

    // Launch order interleaves the (independent) dense GEMM1 into the CSR
    // build chain so that launch index 3 — the one ncu's -s 5 -c 1 capture
    // lands on — is sgemm1, giving us the profile of the dominant kernel.
    // Dependencies respected: spmm128 needs {sgemm1, scatter}; scatter needs
    // {scan1..3, hist}; all on one stream (sequential), so any order works.
    zdeg_kernel<<<nb, 256>>>(M);                          // 0
    hist_kernel<<<(E + 255) / 256, 256>>>(ed, E);         // 1
    scan1_kernel<<<nb, 256>>>(M);                         // 2
    sgemm1_kernel<<<(M + BM - 1) / BM, 256>>>(x, W1, p_xw1, M);  // 3 <- profiled
    scan2_kernel<<<1, 256>>>(nb);                         // 4
    scan3_kernel<<<nb, 256>>>(M);                         // 5
    scatter_kernel<<<(E + 255) / 256, 256>>>(es, ed, ev, E);     // 6

    // --- layer 1 aggregation ---
    spmm128_csr_kernel<<<(M * 32 + 255) / 256, 256>>>(p_xw1, p_acc1, M);

    // --- layer 2 ---
    gemm2_kernel<<<(M + G2_ROWS - 1) / G2_ROWS, 256, g2_smem>>>(
        p_acc1, b1, W2, p_hw2, M);
    spmm40_lsm_kernel<<<(M * 16 + 255) / 256, 256>>>(p_hw2, b2, out, M);
}

// round 10
// speedup vs baseline: 1.9600x; 1.3769x over previous
#include <cuda_runtime.h>
#include <cuda_bf16.h>
#include <math.h>
#include <stdint.h>

// Problem constants (from reference)
#define NNODES 50000
#define NFEAT  512
#define NHID   128
#define NCLASS 40
#define MAXE   1600000

// Scratch (device globals: the sanctioned no-alloc workspace)
__device__ float g_xw1 [NNODES * NHID];   // x @ W1
__device__ float g_acc1[NNODES * NHID];   // spmm(x@W1)
__device__ float g_hw2 [NNODES * NCLASS]; // relu(acc1+b1) @ W2

// CSR workspace
__device__ int   g_deg [NNODES];
__device__ int   g_off [NNODES + 1];
__device__ int   g_pos [NNODES];
__device__ int   g_bsum[256];
__device__ int   g_csrc[MAXE];
__device__ float g_cw  [MAXE];

// ---------------------------------------------------------------------------
// Packed fp32x2 FMA (sm_100+)
// ---------------------------------------------------------------------------
__device__ __forceinline__ float2 ffma2(float2 a, float2 b, float2 c) {
    unsigned long long ua = *(unsigned long long*)&a;
    unsigned long long ub = *(unsigned long long*)&b;
    unsigned long long uc = *(unsigned long long*)&c;
    unsigned long long ud;
    asm("fma.rn.f32x2 %0, %1, %2, %3;" : "=l"(ud) : "l"(ua), "l"(ub), "l"(uc));
    return *(float2*)&ud;
}

__device__ __forceinline__ uint32_t pack_bf16(float lo, float hi) {
    __nv_bfloat162 t = __floats2bfloat162_rn(lo, hi);  // .x = lo (low half)
    return *(uint32_t*)&t;
}

// mma.sync m16n8k16 bf16 -> f32, accumulate in place (sm_80+, HMMA)
__device__ __forceinline__ void mma_bf16(float d[4], const uint32_t a[4],
                                         const uint32_t b[2]) {
    asm volatile(
        "mma.sync.aligned.m16n8k16.row.col.f32.bf16.bf16.f32 "
        "{%0,%1,%2,%3}, {%4,%5,%6,%7}, {%8,%9}, {%0,%1,%2,%3};"
        : "+f"(d[0]), "+f"(d[1]), "+f"(d[2]), "+f"(d[3])
        : "r"(a[0]), "r"(a[1]), "r"(a[2]), "r"(a[3]), "r"(b[0]), "r"(b[1]));
}

// ===========================================================================
// GEMM1 via mma.sync (bf16 3-term split): C[M,128] = A[M,512] @ W1[512,128]
// CTA tile 128x128, BK=32 fp32 per chunk -> bf16 hi/lo smem tiles.
// 8 warps, warp tile 64x32 (warpM = wid&1, warpN = wid>>1).
// Smem layouts: As[m][k] (pad 34), Bs[n][k] (pad 34) -> every fragment reg is
// one contiguous b32 LDS at the PTX-documented (lane>>2, lane&3) coords.
// ===========================================================================
#define BM1 128
#define BK1 32
#define KPAD 34

__global__ __launch_bounds__(256) void gemm1_mma_kernel(
    const float* __restrict__ A, const float* __restrict__ W1,
    float* __restrict__ C, int M)
{
    __shared__ __nv_bfloat16 Ah[BM1][KPAD];
    __shared__ __nv_bfloat16 Al[BM1][KPAD];
    __shared__ __nv_bfloat16 Bh[NHID][KPAD];
    __shared__ __nv_bfloat16 Bl[NHID][KPAD];

    int tid  = threadIdx.x;
    int wid  = tid >> 5;
    int lane = tid & 31;
    int gid  = lane >> 2;     // group id 0..7
    int tq   = lane & 3;      // thread in quad 0..3
    int warpM = wid & 1;      // 0..1
    int warpN = wid >> 1;     // 0..3
    int block_row = blockIdx.x * BM1;

    // accumulators: 4 m-frags x 4 n-frags x 4 f32
    float acc[4][4][4];
#pragma unroll
    for (int i = 0; i < 4; i++)
#pragma unroll
        for (int j = 0; j < 4; j++)
#pragma unroll
            for (int q = 0; q < 4; q++) acc[i][j][q] = 0.f;

    // A-tile load mapping: 1024 float4 / 256 thr = 4 each
    // idx -> row = idx>>3, kq = (idx&7)*4
    // B-tile load mapping: thread n = tid&127, k half = (tid>>7)*16
    int bn  = tid & 127;
    int bkh = (tid >> 7) * 16;

    for (int kc = 0; kc < NFEAT; kc += BK1) {
        // ---- stage A chunk (fp32 -> bf16 hi/lo) ----
#pragma unroll
        for (int i = 0; i < 4; i++) {
            int idx = i * 256 + tid;
            int r   = idx >> 3;
            int kq  = (idx & 7) * 4;
            int grow = block_row + r;
            float4 v = (grow < M)
                ? *(const float4*)(A + (size_t)grow * NFEAT + kc + kq)
                : make_float4(0.f, 0.f, 0.f, 0.f);
            float hx = __bfloat162float(__float2bfloat16_rn(v.x));
            float hy = __bfloat162float(__float2bfloat16_rn(v.y));
            float hz = __bfloat162float(__float2bfloat16_rn(v.z));
            float hw = __bfloat162float(__float2bfloat16_rn(v.w));
            *(uint32_t*)&Ah[r][kq]     = pack_bf16(v.x, v.y);
            *(uint32_t*)&Ah[r][kq + 2] = pack_bf16(v.z, v.w);
            *(uint32_t*)&Al[r][kq]     = pack_bf16(v.x - hx, v.y - hy);
            *(uint32_t*)&Al[r][kq + 2] = pack_bf16(v.z - hz, v.w - hw);
        }
        // ---- stage B chunk transposed: Bs[n][k] = W1[kc+k][n] ----
#pragma unroll
        for (int i = 0; i < 8; i++) {
            int k = bkh + 2 * i;
            float w0 = W1[(size_t)(kc + k)     * NHID + bn];
            float w1 = W1[(size_t)(kc + k + 1) * NHID + bn];
            float h0 = __bfloat162float(__float2bfloat16_rn(w0));
            float h1 = __bfloat162float(__float2bfloat16_rn(w1));
            *(uint32_t*)&Bh[bn][k] = pack_bf16(w0, w1);
            *(uint32_t*)&Bl[bn][k] = pack_bf16(w0 - h0, w1 - h1);
        }
        __syncthreads();

        // ---- compute: 2 k16-steps ----
#pragma unroll
        for (int s = 0; s < 2; s++) {
            int kb = s * 16 + tq * 2;
            uint32_t ah[4][4], al[4][4], bh[4][2], bl[4][2];
#pragma unroll
            for (int mi = 0; mi < 4; mi++) {
                int r0 = warpM * 64 + mi * 16 + gid;
                ah[mi][0] = *(uint32_t*)&Ah[r0][kb];
                ah[mi][1] = *(uint32_t*)&Ah[r0 + 8][kb];
                ah[mi][2] = *(uint32_t*)&Ah[r0][kb + 8];
                ah[mi][3] = *(uint32_t*)&Ah[r0 + 8][kb + 8];
                al[mi][0] = *(uint32_t*)&Al[r0][kb];
                al[mi][1] = *(uint32_t*)&Al[r0 + 8][kb];
                al[mi][2] = *(uint32_t*)&Al[r0][kb + 8];
                al[mi][3] = *(uint32_t*)&Al[r0 + 8][kb + 8];
            }
#pragma unroll
            for (int ni = 0; ni < 4; ni++) {
                int n0 = warpN * 32 + ni * 8 + gid;
                bh[ni][0] = *(uint32_t*)&Bh[n0][kb];
                bh[ni][1] = *(uint32_t*)&Bh[n0][kb + 8];
                bl[ni][0] = *(uint32_t*)&Bl[n0][kb];
                bl[ni][1] = *(uint32_t*)&Bl[n0][kb + 8];
            }
#pragma unroll
            for (int mi = 0; mi < 4; mi++)
#pragma unroll
                for (int ni = 0; ni < 4; ni++) {
                    mma_bf16(acc[mi][ni], ah[mi], bh[ni]);
                    mma_bf16(acc[mi][ni], ah[mi], bl[ni]);
                    mma_bf16(acc[mi][ni], al[mi], bh[ni]);
                }
        }
        __syncthreads();
    }

    // ---- epilogue: direct STG (float2 per fragment half) ----
#pragma unroll
    for (int mi = 0; mi < 4; mi++) {
        int r0 = block_row + warpM * 64 + mi * 16 + gid;
        int r1 = r0 + 8;
#pragma unroll
        for (int ni = 0; ni < 4; ni++) {
            int col = warpN * 32 + ni * 8 + tq * 2;
            if (r0 < M)
                *(float2*)(C + (size_t)r0 * NHID + col) =
                    make_float2(acc[mi][ni][0], acc[mi][ni][1]);
            if (r1 < M)
                *(float2*)(C + (size_t)r1 * NHID + col) =
                    make_float2(acc[mi][ni][2], acc[mi][ni][3]);
        }
    }
}

// ===========================================================================
// CSR construction: zero-deg -> histogram -> 3-step scan -> scatter
// ===========================================================================
__global__ void zdeg_kernel(int n) {
    int i = blockIdx.x * blockDim.x + threadIdx.x;
    if (i < n) g_deg[i] = 0;
}

__global__ void hist_kernel(const int* __restrict__ ed, int E) {
    int e = blockIdx.x * blockDim.x + threadIdx.x;
    if (e < E) atomicAdd(&g_deg[ed[e]], 1);
}

__global__ void scan1_kernel(int n) {          // per-block inclusive scan
    __shared__ int sh[256];
    int t = threadIdx.x, i = blockIdx.x * 256 + t;
    int v = (i < n) ? g_deg[i] : 0;
    sh[t] = v; __syncthreads();
    for (int o = 1; o < 256; o <<= 1) {
        int u = (t >= o) ? sh[t - o] : 0;
        __syncthreads();
        sh[t] += u;
        __syncthreads();
    }
    if (i < n) g_off[i + 1] = sh[t];
    if (t == 255) g_bsum[blockIdx.x] = sh[255];
}

__global__ void scan2_kernel(int nb) {         // exclusive scan of block sums
    __shared__ int sh[256];
    int t = threadIdx.x;
    sh[t] = (t < nb) ? g_bsum[t] : 0; __syncthreads();
    for (int o = 1; o < 256; o <<= 1) {
        int u = (t >= o) ? sh[t - o] : 0;
        __syncthreads();
        sh[t] += u;
        __syncthreads();
    }
    int excl = (t == 0) ? 0 : sh[t - 1];
    if (t < nb) g_bsum[t] = excl;
}

__global__ void scan3_kernel(int n) {          // add block prefix; zero cursors
    int i = blockIdx.x * 256 + threadIdx.x;
    if (i < n) {
        g_off[i + 1] += g_bsum[blockIdx.x];
        g_pos[i] = 0;
    }
    if (i == 0) g_off[0] = 0;
}

__global__ void scatter_kernel(const int* __restrict__ es,
                               const int* __restrict__ ed,
                               const float* __restrict__ ev, int E) {
    int e = blockIdx.x * blockDim.x + threadIdx.x;
    if (e >= E) return;
    int d = ed[e];
    int idx = g_off[d] + atomicAdd(&g_pos[d], 1);
    g_csrc[idx] = es[e];
    g_cw[idx]   = ev[e];
}

// ---------------------------------------------------------------------------
// SpMM (128 feats) over CSR: one warp per dst row, register accumulation.
// ---------------------------------------------------------------------------
__global__ void spmm128_csr_kernel(const float* __restrict__ feat,
                                   float* __restrict__ out, int M)
{
    int warp = (blockIdx.x * blockDim.x + threadIdx.x) >> 5;
    int lane = threadIdx.x & 31;
    if (warp >= M) return;
    int beg = g_off[warp], end = g_off[warp + 1];

    const float* base = feat + lane * 4;
    float2 a0 = make_float2(0.f, 0.f), a1 = make_float2(0.f, 0.f);

    int j = beg;
    for (; j + 4 <= end; j += 4) {
        int   s0 = g_csrc[j],     s1 = g_csrc[j + 1];
        int   s2 = g_csrc[j + 2], s3 = g_csrc[j + 3];
        float w0 = g_cw[j],     w1 = g_cw[j + 1];
        float w2 = g_cw[j + 2], w3 = g_cw[j + 3];
        float4 v0 = *(const float4*)(base + (size_t)s0 * NHID);
        float4 v1 = *(const float4*)(base + (size_t)s1 * NHID);
        float4 v2 = *(const float4*)(base + (size_t)s2 * NHID);
        float4 v3 = *(const float4*)(base + (size_t)s3 * NHID);
        a0 = ffma2(make_float2(w0, w0), make_float2(v0.x, v0.y), a0);
        a1 = ffma2(make_float2(w0, w0), make_float2(v0.z, v0.w), a1);
        a0 = ffma2(make_float2(w1, w1), make_float2(v1.x, v1.y), a0);
        a1 = ffma2(make_float2(w1, w1), make_float2(v1.z, v1.w), a1);
        a0 = ffma2(make_float2(w2, w2), make_float2(v2.x, v2.y), a0);
        a1 = ffma2(make_float2(w2, w2), make_float2(v2.z, v2.w), a1);
        a0 = ffma2(make_float2(w3, w3), make_float2(v3.x, v3.y), a0);
        a1 = ffma2(make_float2(w3, w3), make_float2(v3.z, v3.w), a1);
    }
    for (; j < end; j++) {
        int   s = g_csrc[j];
        float w = g_cw[j];
        float4 v = *(const float4*)(base + (size_t)s * NHID);
        a0 = ffma2(make_float2(w, w), make_float2(v.x, v.y), a0);
        a1 = ffma2(make_float2(w, w), make_float2(v.z, v.w), a1);
    }

    float4 r = make_float4(a0.x, a0.y, a1.x, a1.y);
    *(float4*)(out + (size_t)warp * NHID + lane * 4) = r;
}

// ---------------------------------------------------------------------------
// SpMM (40 feats) over CSR, FUSED with +b2 and log_softmax.
// ---------------------------------------------------------------------------
__global__ void spmm40_lsm_kernel(const float* __restrict__ feat,
                                  const float* __restrict__ b2,
                                  float* __restrict__ out, int M)
{
    int g    = (blockIdx.x * blockDim.x + threadIdx.x) >> 4;
    int l16  = threadIdx.x & 15;
    if (g >= M) return;
    int beg = g_off[g], end = g_off[g + 1];
    bool act = l16 < 10;

    const float* base = feat + l16 * 4;
    float2 a0 = make_float2(0.f, 0.f), a1 = make_float2(0.f, 0.f);
    float4 z = make_float4(0.f, 0.f, 0.f, 0.f);

    int j = beg;
    for (; j + 4 <= end; j += 4) {
        int   s0 = g_csrc[j],     s1 = g_csrc[j + 1];
        int   s2 = g_csrc[j + 2], s3 = g_csrc[j + 3];
        float w0 = g_cw[j],     w1 = g_cw[j + 1];
        float w2 = g_cw[j + 2], w3 = g_cw[j + 3];
        float4 v0 = act ? *(const float4*)(base + (size_t)s0 * NCLASS) : z;
        float4 v1 = act ? *(const float4*)(base + (size_t)s1 * NCLASS) : z;
        float4 v2 = act ? *(const float4*)(base + (size_t)s2 * NCLASS) : z;
        float4 v3 = act ? *(const float4*)(base + (size_t)s3 * NCLASS) : z;
        a0 = ffma2(make_float2(w0, w0), make_float2(v0.x, v0.y), a0);
        a1 = ffma2(make_float2(w0, w0), make_float2(v0.z, v0.w), a1);
        a0 = ffma2(make_float2(w1, w1), make_float2(v1.x, v1.y), a0);
        a1 = ffma2(make_float2(w1, w1), make_float2(v1.z, v1.w), a1);
        a0 = ffma2(make_float2(w2, w2), make_float2(v2.x, v2.y), a0);
        a1 = ffma2(make_float2(w2, w2), make_float2(v2.z, v2.w), a1);
        a0 = ffma2(make_float2(w3, w3), make_float2(v3.x, v3.y), a0);
        a1 = ffma2(make_float2(w3, w3), make_float2(v3.z, v3.w), a1);
    }
    for (; j < end; j++) {
        int   s = g_csrc[j];
        float w = g_cw[j];
        float4 v = act ? *(const float4*)(base + (size_t)s * NCLASS) : z;
        a0 = ffma2(make_float2(w, w), make_float2(v.x, v.y), a0);
        a1 = ffma2(make_float2(w, w), make_float2(v.z, v.w), a1);
    }

    float4 lv;
    if (act) {
        float4 b = *(const float4*)(b2 + l16 * 4);
        lv = make_float4(a0.x + b.x, a0.y + b.y, a1.x + b.z, a1.y + b.w);
    } else {
        lv = make_float4(-INFINITY, -INFINITY, -INFINITY, -INFINITY);
    }

    float m = fmaxf(fmaxf(lv.x, lv.y), fmaxf(lv.z, lv.w));
#pragma unroll
    for (int o = 8; o > 0; o >>= 1)
        m = fmaxf(m, __shfl_xor_sync(0xFFFFFFFFu, m, o, 16));

    float s = act ? (expf(lv.x - m) + expf(lv.y - m) +
                     expf(lv.z - m) + expf(lv.w - m)) : 0.f;
#pragma unroll
    for (int o = 8; o > 0; o >>= 1)
        s += __shfl_xor_sync(0xFFFFFFFFu, s, o, 16);

    float lse = m + logf(s);

    if (act) {
        float4 r = make_float4(lv.x - lse, lv.y - lse, lv.z - lse, lv.w - lse);
        *(float4*)(out + (size_t)g * NCLASS + l16 * 4) = r;
    }
}

// ---------------------------------------------------------------------------
// GEMM2: hw2[r,:] = relu(acc1[r,:] + b1) @ W2   (M x 128 @ 128 x 40)
// ---------------------------------------------------------------------------
#define G2_ROWS 64
#define G2_APAD 132
#define G2_SMEM_FLOATS (NHID * NCLASS + G2_ROWS * G2_APAD)

__global__ __launch_bounds__(256) void gemm2_kernel(
    const float* __restrict__ acc1, const float* __restrict__ b1,
    const float* __restrict__ W2, float* __restrict__ hw2, int M)
{
    extern __shared__ float sm[];
    float* Ws = sm;                     // [128][40]
    float* At = sm + NHID * NCLASS;     // [64][132]

    int tid = threadIdx.x;
    int row0 = blockIdx.x * G2_ROWS;

#pragma unroll
    for (int i = 0; i < NHID * NCLASS / 256; i++)
        Ws[tid + i * 256] = W2[tid + i * 256];

#pragma unroll
    for (int i = 0; i < G2_ROWS * NHID / (256 * 4); i++) {
        int idx4 = tid + i * 256;
        int r    = idx4 >> 5;
        int c4   = idx4 & 31;
        int grow = row0 + r;
        float4 v = (grow < M)
            ? *(const float4*)(acc1 + (size_t)grow * NHID + c4 * 4)
            : make_float4(0.f, 0.f, 0.f, 0.f);
        float4 b = *(const float4*)(b1 + c4 * 4);
        float4 h;
        h.x = fmaxf(v.x + b.x, 0.f);
        h.y = fmaxf(v.y + b.y, 0.f);
        h.z = fmaxf(v.z + b.z, 0.f);
        h.w = fmaxf(v.w + b.w, 0.f);
        *(float4*)(At + r * G2_APAD + c4 * 4) = h;
    }
    __syncthreads();

    int r  = tid >> 2;
    int qc = (tid & 3) * 10;

    float2 acc[5];
#pragma unroll
    for (int j = 0; j < 5; j++) acc[j] = make_float2(0.f, 0.f);

    const float* arow = At + r * G2_APAD;
#pragma unroll 4
    for (int k = 0; k < NHID; k += 4) {
        float4 h4 = *(const float4*)(arow + k);
#pragma unroll
        for (int kk = 0; kk < 4; kk++) {
            float h = (&h4.x)[kk];
            float2 h2 = make_float2(h, h);
            const float* wrow = Ws + (k + kk) * NCLASS + qc;
#pragma unroll
            for (int j = 0; j < 5; j++)
                acc[j] = ffma2(h2, *(const float2*)(wrow + j * 2), acc[j]);
        }
    }

    int grow = row0 + r;
    if (grow < M) {
        float* o = hw2 + (size_t)grow * NCLASS + qc;
#pragma unroll
        for (int j = 0; j < 5; j++)
            *(float2*)(o + j * 2) = acc[j];
    }
}

// ---------------------------------------------------------------------------

extern "C" void kernel_launch(void* const* d_in, const int* in_sizes, int n_in,
                              void* d_out, int out_size)
{
    const float* x  = (const float*)d_in[0];
    const float* W1 = (const float*)d_in[1];
    const float* b1 = (const float*)d_in[2];
    const float* W2 = (const float*)d_in[3];
    const float* b2 = (const float*)d_in[4];
    const int*   es = (const int*)d_in[5];
    const int*   ed = (const int*)d_in[6];
    const float* ev = (const float*)d_in[7];
    int E = in_sizes[5];
    float* out = (float*)d_out;
    int M = NNODES;

    float *p_xw1, *p_acc1, *p_hw2;
    cudaGetSymbolAddress((void**)&p_xw1,  g_xw1);
    cudaGetSymbolAddress((void**)&p_acc1, g_acc1);
    cudaGetSymbolAddress((void**)&p_hw2,  g_hw2);

    const int g2_smem = G2_SMEM_FLOATS * sizeof(float);
    cudaFuncSetAttribute(gemm2_kernel,
                         cudaFuncAttributeMaxDynamicSharedMemorySize, g2_smem);

    int nb = (M + 255) / 256;   // 196 blocks (<=256 required by scan2)

    // Launch index 3 = gemm1_mma (the one ncu -s 5 -c 1 profiles).
    zdeg_kernel<<<nb, 256>>>(M);                          // 0
    hist_kernel<<<(E + 255) / 256, 256>>>(ed, E);         // 1
    scan1_kernel<<<nb, 256>>>(M);                         // 2
    gemm1_mma_kernel<<<(M + BM1 - 1) / BM1, 256>>>(x, W1, p_xw1, M);  // 3
    scan2_kernel<<<1, 256>>>(nb);                         // 4
    scan3_kernel<<<nb, 256>>>(M);                         // 5
    scatter_kernel<<<(E + 255) / 256, 256>>>(es, ed, ev, E);     // 6

    // --- layer 1 aggregation ---
    spmm128_csr_kernel<<<(M * 32 + 255) / 256, 256>>>(p_xw1, p_acc1, M);

    // --- layer 2 ---
    gemm2_kernel<<<(M + G2_ROWS - 1) / G2_ROWS, 256, g2_smem>>>(
        p_acc1, b1, W2, p_hw2, M);
    spmm40_lsm_kernel<<<(M * 16 + 255) / 256, 256>>>(p_hw2, b2, out, M);
}